// round 10
// baseline (speedup 1.0000x reference)
#include <cuda_runtime.h>
#include <cuda_fp16.h>
#include <math.h>
#include <stdint.h>

#define DV     256
#define O_MAX  50000
#define E_MAX  200000
#define CONSTV 10.0f

// ---------------- static device scratch ----------------
__device__ float g_P[(size_t)O_MAX * 1024];     // X@W1' : [O,1024] fp32
__device__ float g_m[O_MAX];
__device__ float g_Ws[O_MAX];
__device__ float g_Wo[O_MAX];
__device__ int   g_pairs[2 * E_MAX];
__device__ int   g_is64;
__device__ int   g_cnt[O_MAX];
__device__ int   g_off[O_MAX + 1];
__device__ int   g_cur[O_MAX];
__device__ int2  g_items[2 * E_MAX];

// stacked-K fp16 operands (hi|lo along K)
__device__ __half g_XA2[(size_t)O_MAX * 512];   // [O][512]:  k<256 hi(X), k>=256 lo(X)
__device__ __half g_HA2[(size_t)O_MAX * 2048];  // [O][2048]: k<1024 hi(H), else lo(H)
__device__ __half g_W1Ts[1024 * 512];           // [1024][512]:  W1p^T duplicated along K
__device__ __half g_W2Ts[256 * 2048];           // [256][2048]:  W2p^T duplicated along K

// ---------------- helpers ----------------
__device__ __forceinline__ uint32_t smem_u32(const void* p) {
    uint32_t a;
    asm("{ .reg .u64 t; cvta.to.shared.u64 t, %1; cvt.u32.u64 %0, t; }" : "=r"(a) : "l"(p));
    return a;
}
__device__ __forceinline__ void ldsm_x4(uint32_t* r, uint32_t addr) {
    asm volatile("ldmatrix.sync.aligned.m8n8.x4.shared.b16 {%0,%1,%2,%3}, [%4];"
                 : "=r"(r[0]), "=r"(r[1]), "=r"(r[2]), "=r"(r[3]) : "r"(addr));
}
__device__ __forceinline__ void mma16816(float* d, const uint32_t* a, uint32_t b0,
                                         uint32_t b1) {
    asm volatile(
        "mma.sync.aligned.m16n8k16.row.col.f32.f16.f16.f32 "
        "{%0,%1,%2,%3}, {%4,%5,%6,%7}, {%8,%9}, {%0,%1,%2,%3};"
        : "+f"(d[0]), "+f"(d[1]), "+f"(d[2]), "+f"(d[3])
        : "r"(a[0]), "r"(a[1]), "r"(a[2]), "r"(a[3]), "r"(b0), "r"(b1));
}
__device__ __forceinline__ void cp16(uint32_t dst, const void* src, int pbytes) {
    asm volatile("cp.async.cg.shared.global [%0], [%1], 16, %2;"
                 :: "r"(dst), "l"(src), "r"(pbytes));
}
#define CP_COMMIT() asm volatile("cp.async.commit_group;" ::: "memory")
#define CP_WAIT(n)  asm volatile("cp.async.wait_group %0;" :: "n"(n) : "memory")

// swizzled byte offset inside a 128-row x 128-byte tile
__device__ __forceinline__ uint32_t swz(int r, int c16) {
    uint32_t off = (uint32_t)(r * 128 + c16 * 16);
    return off ^ ((off >> 3) & 0x70);
}

__device__ __forceinline__ void split2h(float x, __half& h, __half& l) {
    h = __float2half_rn(x);
    l = __float2half_rn(x - __half2float(h));
}

// ---------------- setup kernels ----------------

// weights: repack + transpose + fp16 + duplicate along K, directly from W1/W2.
// g_W1Ts[nn][k'] = fp16(W1p[k' % 256][nn]),  W1p[k][nn] = nn<512 ? W1[k][nn] : W1[k+256][nn-512]
// g_W2Ts[nn][k'] = fp16(W2p[k' % 1024][nn]), W2p[k][nn] = k<512 ? W2[k][nn] : W2[k-512][nn+256]
__global__ void w_kernel(const float* __restrict__ W1, const float* __restrict__ W2) {
    int i = blockIdx.x * blockDim.x + threadIdx.x;
    if (i < 1024 * 512) {
        int nn = i >> 9, kp = i & 511, k = kp & 255;
        float v = (nn < 512) ? W1[k * 512 + nn] : W1[(k + 256) * 512 + (nn - 512)];
        g_W1Ts[i] = __float2half_rn(v);
    }
    if (i < 256 * 2048) {
        int nn = i >> 11, kp = i & 2047, k = kp & 1023;
        float v = (k < 512) ? W2[k * 512 + nn] : W2[(k - 512) * 512 + (nn + 256)];
        g_W2Ts[i] = __float2half_rn(v);
    }
}

// X -> stacked hi|lo fp16 rows
__global__ void split_x_kernel(const float* __restrict__ X, int npairs) {  // O*128
    for (int i = blockIdx.x * blockDim.x + threadIdx.x; i < npairs;
         i += gridDim.x * blockDim.x) {
        float2 v = reinterpret_cast<const float2*>(X)[i];
        int row = i >> 7, cp = (i & 127) * 2;    // col pair
        __half xh, xl, yh, yl;
        split2h(v.x, xh, xl);
        split2h(v.y, yh, yl);
        __half2* R = reinterpret_cast<__half2*>(g_XA2 + (size_t)row * 512);
        R[cp >> 1]         = __halves2half2(xh, yh);
        R[(256 + cp) >> 1] = __halves2half2(xl, yl);
    }
}

// init + pairs-dtype detect (block 0 thread 0)
__global__ void init_kernel(const int* __restrict__ p, int O) {
    if (blockIdx.x == 0 && threadIdx.x == 0) {
        int all0 = 1;
        for (int i = 1; i < 129; i += 2)
            if (p[i] != 0) { all0 = 0; break; }
        g_is64 = all0;
    }
    for (int i = blockIdx.x * blockDim.x + threadIdx.x; i < O; i += gridDim.x * blockDim.x) {
        g_m[i] = CONSTV;
        g_cnt[i] = 0;
    }
}

// convert pairs + seg-max conf + incidence count, fused
__global__ void edgecvt_kernel(const int* __restrict__ p, const float* __restrict__ conf,
                               int E) {
    int e = blockIdx.x * blockDim.x + threadIdx.x;
    if (e >= E) return;
    int is64 = g_is64;
    int s = is64 ? p[4 * e]     : p[2 * e];
    int o = is64 ? p[4 * e + 2] : p[2 * e + 1];
    g_pairs[2 * e] = s;
    g_pairs[2 * e + 1] = o;
    float c = conf[e];
    if (c > CONSTV) {
        atomicMax((int*)&g_m[s], __float_as_int(c));
        atomicMax((int*)&g_m[o], __float_as_int(c));
    }
    atomicAdd(&g_cnt[s], 1);
    atomicAdd(&g_cnt[o], 1);
}

__global__ void scan_kernel(int O) {
    __shared__ int warp_sums[32];
    __shared__ int s_carry;
    int tid = threadIdx.x, lane = tid & 31, wid = tid >> 5;
    if (tid == 0) s_carry = 0;
    __syncthreads();
    for (int base = 0; base < O; base += 1024) {
        int i = base + tid;
        int v = (i < O) ? g_cnt[i] : 0;
        int x = v;
#pragma unroll
        for (int d = 1; d < 32; d <<= 1) {
            int t = __shfl_up_sync(0xffffffffu, x, d);
            if (lane >= d) x += t;
        }
        if (lane == 31) warp_sums[wid] = x;
        __syncthreads();
        if (wid == 0) {
            int y = warp_sums[lane];
#pragma unroll
            for (int d = 1; d < 32; d <<= 1) {
                int t = __shfl_up_sync(0xffffffffu, y, d);
                if (lane >= d) y += t;
            }
            warp_sums[lane] = y;
        }
        __syncthreads();
        int incl = x + (wid ? warp_sums[wid - 1] : 0);
        int excl = s_carry + incl - v;
        if (i < O) { g_off[i] = excl; g_cur[i] = excl; }
        __syncthreads();
        if (tid == 1023) s_carry += incl;
        __syncthreads();
    }
    if (tid == 0) g_off[O] = s_carry;
}

__global__ void fill_kernel(const float* __restrict__ conf, int E) {
    int e = blockIdx.x * blockDim.x + threadIdx.x;
    if (e >= E) return;
    int s = g_pairs[2 * e], o = g_pairs[2 * e + 1];
    int cb = __float_as_int(conf[e]);
    g_items[atomicAdd(&g_cur[s], 1)] = make_int2((o << 1) | 0, cb);
    g_items[atomicAdd(&g_cur[o], 1)] = make_int2((s << 1) | 1, cb);
}

// ---------------- pipelined HMMA GEMM (single fp16 plane, stacked K) ----------------
// C[M,N] = A @ B^T, A:[M,K] fp16 row-major, B:[N,K] fp16 row-major.
// 128x128 CTA tile, 8 warps (32x64), BK=64 chunks, 2-stage cp.async, 32KB/stage.
// EPI==0: plain fp32 store. EPI==1: fused BGConv epilogue.
template <int EPI>
__global__ void __launch_bounds__(256, 2)
mma_gemm(const __half* __restrict__ Ab, const __half* __restrict__ Bb,
         float* __restrict__ C, int M, int N, int K,
         const float* __restrict__ X, const float* __restrict__ b2) {
    extern __shared__ __align__(1024) char smem[];
    const uint32_t su = smem_u32(smem);

    int tid = threadIdx.x, lane = tid & 31, wid = tid >> 5;
    int bm0 = blockIdx.y * 128, bn0 = blockIdx.x * 128;
    int wm = (wid & 3) * 32;
    int wn = (wid >> 2) * 64;

    float d[2][8][4];
#pragma unroll
    for (int mt = 0; mt < 2; mt++)
#pragma unroll
        for (int nt = 0; nt < 8; nt++)
#pragma unroll
            for (int q = 0; q < 4; q++) d[mt][nt][q] = 0.f;

    int cpt = K >> 6;

    auto load_chunk = [&](int c, int stage) {
        int kk = c << 6;
#pragma unroll
        for (int l = 0; l < 8; l++) {
            int i = tid + l * 256;                   // 0..2047
            int isB = i >> 10;
            int j = i & 1023;
            int r = j >> 3, u = j & 7;
            int col0 = kk + u * 8;
            uint32_t dst = su + stage * 32768 + isB * 16384 + swz(r, u);
            if (isB) {
                cp16(dst, Bb + (size_t)(bn0 + r) * K + col0, 16);
            } else {
                int grow = bm0 + r;
                int pb = (grow < M) ? 16 : 0;
                if (grow >= M) grow = M - 1;
                cp16(dst, Ab + (size_t)grow * K + col0, pb);
            }
        }
        CP_COMMIT();
    };

    load_chunk(0, 0);

    for (int c = 0; c < cpt; ++c) {
        int stage = c & 1;
        if (c + 1 < cpt) {
            load_chunk(c + 1, stage ^ 1);
            CP_WAIT(1);
        } else {
            CP_WAIT(0);
        }
        __syncthreads();

        uint32_t a_base = su + stage * 32768;
        uint32_t b_base = a_base + 16384;

#pragma unroll
        for (int ks = 0; ks < 4; ks++) {
            int c16 = ks * 2 + (lane >> 4);
            uint32_t a[2][4], bb[4];
#pragma unroll
            for (int mt = 0; mt < 2; mt++)
                ldsm_x4(a[mt], a_base + swz(wm + mt * 16 + (lane & 15), c16));
#pragma unroll
            for (int nt4 = 0; nt4 < 4; nt4++) {
                ldsm_x4(bb, b_base + swz(wn + nt4 * 16 + (lane & 15), c16));
                mma16816(d[0][2 * nt4],     a[0], bb[0], bb[2]);
                mma16816(d[0][2 * nt4 + 1], a[0], bb[1], bb[3]);
                mma16816(d[1][2 * nt4],     a[1], bb[0], bb[2]);
                mma16816(d[1][2 * nt4 + 1], a[1], bb[1], bb[3]);
            }
        }
        __syncthreads();
    }

    // epilogue (fragment mapping verified R7-R9)
    int group = lane >> 2, quad = lane & 3;
#pragma unroll
    for (int mt = 0; mt < 2; mt++) {
#pragma unroll
        for (int half = 0; half < 2; half++) {
            int row = bm0 + wm + mt * 16 + group + half * 8;
            if (row >= M) continue;
            float ws = 0.f, wo = 0.f, swf = 0.f, inv = 1.f;
            if (EPI == 1) {
                ws = g_Ws[row]; wo = g_Wo[row];
                swf = expf(CONSTV - g_m[row]);
                inv = 1.f / (ws + wo + swf);
            }
#pragma unroll
            for (int nt = 0; nt < 8; nt++) {
                int col = bn0 + wn + nt * 8 + quad * 2;
                float v0 = d[mt][nt][half * 2 + 0];
                float v1 = d[mt][nt][half * 2 + 1];
                if (EPI == 1) {
                    v0 = (v0 + ws * b2[col]     + wo * b2[col + DV]
                          + swf * X[(size_t)row * DV + col]) * inv;
                    v1 = (v1 + ws * b2[col + 1] + wo * b2[col + 1 + DV]
                          + swf * X[(size_t)row * DV + col + 1]) * inv;
                }
                *reinterpret_cast<float2*>(&C[(size_t)row * N + col]) = make_float2(v0, v1);
            }
        }
    }
}

// ---------------- node-centric accumulation; emits stacked H fp16 rows ----------------
__device__ __forceinline__ void store_split4(__half2* row, int e0, float4 v) {
    __half a0, a1, b0, b1, c0, c1, d0, d1;
    split2h(v.x, a0, a1); split2h(v.y, b0, b1);
    split2h(v.z, c0, c1); split2h(v.w, d0, d1);
    int h = e0 >> 1;
    row[h]     = __halves2half2(a0, b0);  row[h + 1]       = __halves2half2(c0, d0);
    row[h + 512] = __halves2half2(a1, b1); row[h + 513]    = __halves2half2(c1, d1);
}

__global__ void node_kernel(const float* __restrict__ b1, int O) {
    int n    = (blockIdx.x * blockDim.x + threadIdx.x) >> 5;
    int lane = threadIdx.x & 31;
    if (n >= O) return;

    const float4* Pn = reinterpret_cast<const float4*>(g_P + (size_t)n * 1024);
    const float4* B1 = reinterpret_cast<const float4*>(b1);
    float4 ps0[4], ps1[4], bv[4], acc0[4], acc1[4];
#pragma unroll
    for (int j = 0; j < 4; j++) {
        int idx = lane + j * 32;
        ps0[j] = Pn[idx];
        ps1[j] = Pn[128 + idx];
        bv[j]  = B1[idx];
        acc0[j] = make_float4(0.f, 0.f, 0.f, 0.f);
        acc1[j] = make_float4(0.f, 0.f, 0.f, 0.f);
    }
    float wssum = 0.f, wosum = 0.f;
    float mn = g_m[n];
    int beg = g_off[n], end = g_off[n + 1];

    int2 rec = (beg < end) ? g_items[beg] : make_int2(0, 0);
    for (int it = beg; it < end; ++it) {
        int2 next = (it + 1 < end) ? g_items[it + 1] : make_int2(0, 0);
        int other = rec.x >> 1, role = rec.x & 1;
        float w = expf(__int_as_float(rec.y) - mn);
        const float4* Po = reinterpret_cast<const float4*>(g_P + (size_t)other * 1024);
        if (role == 0) {
            wssum += w;
#pragma unroll
            for (int j = 0; j < 4; j++) {
                int idx = lane + j * 32;
                float4 q = Po[128 + idx];
                float hx = fmaxf(ps0[j].x + q.x + bv[j].x, 0.f);
                float hy = fmaxf(ps0[j].y + q.y + bv[j].y, 0.f);
                float hz = fmaxf(ps0[j].z + q.z + bv[j].z, 0.f);
                float hw = fmaxf(ps0[j].w + q.w + bv[j].w, 0.f);
                acc0[j].x = fmaf(w, hx, acc0[j].x);
                acc0[j].y = fmaf(w, hy, acc0[j].y);
                acc0[j].z = fmaf(w, hz, acc0[j].z);
                acc0[j].w = fmaf(w, hw, acc0[j].w);
            }
        } else {
            wosum += w;
#pragma unroll
            for (int j = 0; j < 4; j++) {
                int idx = lane + j * 32;
                float4 q = Po[idx];
                float hx = fmaxf(q.x + ps1[j].x + bv[j].x, 0.f);
                float hy = fmaxf(q.y + ps1[j].y + bv[j].y, 0.f);
                float hz = fmaxf(q.z + ps1[j].z + bv[j].z, 0.f);
                float hw = fmaxf(q.w + ps1[j].w + bv[j].w, 0.f);
                acc1[j].x = fmaf(w, hx, acc1[j].x);
                acc1[j].y = fmaf(w, hy, acc1[j].y);
                acc1[j].z = fmaf(w, hz, acc1[j].z);
                acc1[j].w = fmaf(w, hw, acc1[j].w);
            }
        }
        rec = next;
    }

    __half2* Hrow = reinterpret_cast<__half2*>(g_HA2 + (size_t)n * 2048);
#pragma unroll
    for (int j = 0; j < 4; j++) {
        int idx = lane + j * 32;
        store_split4(Hrow, idx * 4, acc0[j]);          // H cols 0..511   -> k 0..511 / lo at +1024
        store_split4(Hrow + 256, idx * 4, acc1[j]);    // H cols 512..1023
    }
    if (lane == 0) { g_Ws[n] = wssum; g_Wo[n] = wosum; }
}

// ---------------- launch ----------------
extern "C" void kernel_launch(void* const* d_in, const int* in_sizes, int n_in,
                              void* d_out, int out_size) {
    const float* X     = (const float*)d_in[0];
    const int*   pairs = (const int*)d_in[1];
    const float* conf  = (const float*)d_in[2];
    const float* W1    = (const float*)d_in[3];
    const float* b1    = (const float*)d_in[4];
    const float* W2    = (const float*)d_in[5];
    const float* b2    = (const float*)d_in[6];
    float*       out   = (float*)d_out;

    int O  = in_sizes[0] / DV;
    int E  = in_sizes[2];
    int MT = (O + 127) / 128;
    const int SMEM = 65536;     // 2 stages x 32KB

    cudaFuncSetAttribute(mma_gemm<0>, cudaFuncAttributeMaxDynamicSharedMemorySize, SMEM);
    cudaFuncSetAttribute(mma_gemm<1>, cudaFuncAttributeMaxDynamicSharedMemorySize, SMEM);

    w_kernel<<<2048, 256>>>(W1, W2);                                     // 1
    split_x_kernel<<<2048, 256>>>(X, O * 128);                           // 2
    init_kernel<<<256, 256>>>(pairs, O);                                 // 3

    // GEMM1: P[O,1024] = [Xhi|Xlo] @ W1Ts^T, K=512   (captured ncu slot)
    mma_gemm<0><<<dim3(8, MT), 256, SMEM>>>(g_XA2, g_W1Ts,
                                            g_P, O, 1024, 512, nullptr, nullptr); // 4

    edgecvt_kernel<<<(E + 255) / 256, 256>>>(pairs, conf, E);            // 5
    scan_kernel<<<1, 1024>>>(O);                                         // 6
    fill_kernel<<<(E + 255) / 256, 256>>>(conf, E);                      // 7
    node_kernel<<<(O + 7) / 8, 256>>>(b1, O);                            // 8

    // GEMM2: out[O,256] = ([Hhi|Hlo] @ W2Ts^T + bias/self)/denom, K=2048
    mma_gemm<1><<<dim3(2, MT), 256, SMEM>>>(g_HA2, g_W2Ts,
                                            out, O, 256, 2048, X, b2);   // 9
}

// round 12
// speedup vs baseline: 1.9423x; 1.9423x over previous
#include <cuda_runtime.h>
#include <cuda_fp16.h>
#include <math.h>
#include <stdint.h>

#define DV     256
#define O_MAX  50000
#define E_MAX  200000
#define CONSTV 10.0f

// ---------------- static device scratch ----------------
__device__ float g_P[(size_t)O_MAX * 1024];     // X@W1' : [O,1024] fp32
__device__ float g_m[O_MAX];
__device__ float g_Ws[O_MAX];
__device__ float g_Wo[O_MAX];
__device__ int   g_pairs[2 * E_MAX];
__device__ int   g_is64;
__device__ int   g_cnt[O_MAX];
__device__ int   g_off[O_MAX + 1];
__device__ int   g_cur[O_MAX];
__device__ int2  g_items[2 * E_MAX];

// fp16 planes: A-side hi/lo (22-bit effective), weights single fp16 plane
#define XSTR ((size_t)O_MAX * 256)
#define HSTR ((size_t)O_MAX * 1024)
__device__ __half g_XA[2 * XSTR];               // X planes  [O,256]
__device__ __half g_HA[2 * HSTR];               // H planes  [O,1024]
__device__ __half g_W1Tf[1024 * 256];           // W1p^T fp16 [1024,256]
__device__ __half g_W2Tf[256 * 1024];           // W2p^T fp16 [256,1024]

// ---------------- helpers ----------------
__device__ __forceinline__ uint32_t smem_u32(const void* p) {
    uint32_t a;
    asm("{ .reg .u64 t; cvta.to.shared.u64 t, %1; cvt.u32.u64 %0, t; }" : "=r"(a) : "l"(p));
    return a;
}
__device__ __forceinline__ void ldsm_x4(uint32_t* r, uint32_t addr) {
    asm volatile("ldmatrix.sync.aligned.m8n8.x4.shared.b16 {%0,%1,%2,%3}, [%4];"
                 : "=r"(r[0]), "=r"(r[1]), "=r"(r[2]), "=r"(r[3]) : "r"(addr));
}
__device__ __forceinline__ void mma16816(float* d, const uint32_t* a, uint32_t b0,
                                         uint32_t b1) {
    asm volatile(
        "mma.sync.aligned.m16n8k16.row.col.f32.f16.f16.f32 "
        "{%0,%1,%2,%3}, {%4,%5,%6,%7}, {%8,%9}, {%0,%1,%2,%3};"
        : "+f"(d[0]), "+f"(d[1]), "+f"(d[2]), "+f"(d[3])
        : "r"(a[0]), "r"(a[1]), "r"(a[2]), "r"(a[3]), "r"(b0), "r"(b1));
}
__device__ __forceinline__ void cp16(uint32_t dst, const void* src, int pbytes) {
    asm volatile("cp.async.cg.shared.global [%0], [%1], 16, %2;"
                 :: "r"(dst), "l"(src), "r"(pbytes));
}
#define CP_COMMIT() asm volatile("cp.async.commit_group;" ::: "memory")
#define CP_WAIT(n)  asm volatile("cp.async.wait_group %0;" :: "n"(n) : "memory")

// swizzled byte offset inside an R-row x 128-byte tile (pattern repeats every 8 rows)
__device__ __forceinline__ uint32_t swz(int r, int c16) {
    uint32_t off = (uint32_t)(r * 128 + c16 * 16);
    return off ^ ((off >> 3) & 0x70);
}

__device__ __forceinline__ void split2h(float x, __half& h, __half& l) {
    h = __float2half_rn(x);
    l = __float2half_rn(x - __half2float(h));
}

// ---------------- setup kernels ----------------

// weights: repack + transpose + fp16, directly from W1/W2 (single plane)
__global__ void w_kernel(const float* __restrict__ W1, const float* __restrict__ W2) {
    int i = blockIdx.x * blockDim.x + threadIdx.x;
    if (i < 1024 * 256) {
        int nn = i >> 8, k = i & 255;                    // W1T [1024,256]
        float v = (nn < 512) ? W1[k * 512 + nn] : W1[(k + 256) * 512 + (nn - 512)];
        g_W1Tf[i] = __float2half_rn(v);
    }
    if (i < 256 * 1024) {
        int nn = i >> 10, k = i & 1023;                  // W2T [256,1024]
        float v = (k < 512) ? W2[k * 512 + nn] : W2[(k - 512) * 512 + (nn + 256)];
        g_W2Tf[i] = __float2half_rn(v);
    }
}

// X -> hi/lo fp16 planes
__global__ void split_x_kernel(const float* __restrict__ X, int npairs) {  // O*128
    for (int i = blockIdx.x * blockDim.x + threadIdx.x; i < npairs;
         i += gridDim.x * blockDim.x) {
        float2 v = reinterpret_cast<const float2*>(X)[i];
        __half xh, xl, yh, yl;
        split2h(v.x, xh, xl);
        split2h(v.y, yh, yl);
        reinterpret_cast<__half2*>(g_XA)[i]        = __halves2half2(xh, yh);
        reinterpret_cast<__half2*>(g_XA + XSTR)[i] = __halves2half2(xl, yl);
    }
}

// init + pairs-dtype detect
__global__ void init_kernel(const int* __restrict__ p, int O) {
    if (blockIdx.x == 0 && threadIdx.x == 0) {
        int all0 = 1;
        for (int i = 1; i < 129; i += 2)
            if (p[i] != 0) { all0 = 0; break; }
        g_is64 = all0;
    }
    for (int i = blockIdx.x * blockDim.x + threadIdx.x; i < O; i += gridDim.x * blockDim.x) {
        g_m[i] = CONSTV;
        g_cnt[i] = 0;
    }
}

// convert pairs + seg-max conf + incidence count, fused
__global__ void edgecvt_kernel(const int* __restrict__ p, const float* __restrict__ conf,
                               int E) {
    int e = blockIdx.x * blockDim.x + threadIdx.x;
    if (e >= E) return;
    int is64 = g_is64;
    int s = is64 ? p[4 * e]     : p[2 * e];
    int o = is64 ? p[4 * e + 2] : p[2 * e + 1];
    g_pairs[2 * e] = s;
    g_pairs[2 * e + 1] = o;
    float c = conf[e];
    if (c > CONSTV) {
        atomicMax((int*)&g_m[s], __float_as_int(c));
        atomicMax((int*)&g_m[o], __float_as_int(c));
    }
    atomicAdd(&g_cnt[s], 1);
    atomicAdd(&g_cnt[o], 1);
}

__global__ void scan_kernel(int O) {
    __shared__ int warp_sums[32];
    __shared__ int s_carry;
    int tid = threadIdx.x, lane = tid & 31, wid = tid >> 5;
    if (tid == 0) s_carry = 0;
    __syncthreads();
    for (int base = 0; base < O; base += 1024) {
        int i = base + tid;
        int v = (i < O) ? g_cnt[i] : 0;
        int x = v;
#pragma unroll
        for (int d = 1; d < 32; d <<= 1) {
            int t = __shfl_up_sync(0xffffffffu, x, d);
            if (lane >= d) x += t;
        }
        if (lane == 31) warp_sums[wid] = x;
        __syncthreads();
        if (wid == 0) {
            int y = warp_sums[lane];
#pragma unroll
            for (int d = 1; d < 32; d <<= 1) {
                int t = __shfl_up_sync(0xffffffffu, y, d);
                if (lane >= d) y += t;
            }
            warp_sums[lane] = y;
        }
        __syncthreads();
        int incl = x + (wid ? warp_sums[wid - 1] : 0);
        int excl = s_carry + incl - v;
        if (i < O) { g_off[i] = excl; g_cur[i] = excl; }
        __syncthreads();
        if (tid == 1023) s_carry += incl;
        __syncthreads();
    }
    if (tid == 0) g_off[O] = s_carry;
}

__global__ void fill_kernel(const float* __restrict__ conf, int E) {
    int e = blockIdx.x * blockDim.x + threadIdx.x;
    if (e >= E) return;
    int s = g_pairs[2 * e], o = g_pairs[2 * e + 1];
    int cb = __float_as_int(conf[e]);
    g_items[atomicAdd(&g_cur[s], 1)] = make_int2((o << 1) | 0, cb);
    g_items[atomicAdd(&g_cur[o], 1)] = make_int2((s << 1) | 1, cb);
}

// ---------------- pipelined HMMA GEMM, fp16 split-2 / 2-term, fat N-tile ----------------
// C[M,N] = (Ahi + Alo) @ B^T.  A planes [M,K], B [N,K] fp16.
// CTA tile 128x256, 8 warps (32x128 each), BK=64 chunks, 2-stage cp.async.
// stage: Ah 16KB + Al 16KB + B 32KB = 64KB; 2 stages = 128KB; 1 CTA/SM.
// EPI==0: plain fp32 store. EPI==1: fused BGConv epilogue.
template <int EPI>
__global__ void __launch_bounds__(256, 1)
mma_gemm(const __half* __restrict__ Ab, size_t apstride,
         const __half* __restrict__ Bb,
         float* __restrict__ C, int M, int N, int K,
         const float* __restrict__ X, const float* __restrict__ b2) {
    extern __shared__ __align__(1024) char smem[];
    const uint32_t su = smem_u32(smem);

    int tid = threadIdx.x, lane = tid & 31, wid = tid >> 5;
    int bm0 = blockIdx.y * 128, bn0 = blockIdx.x * 256;
    int wm = (wid & 3) * 32;          // warp m-offset
    int wn = (wid >> 2) * 128;        // warp n-offset (2 warps cover 256)

    float d[2][16][4];
#pragma unroll
    for (int mt = 0; mt < 2; mt++)
#pragma unroll
        for (int nt = 0; nt < 16; nt++)
#pragma unroll
            for (int q = 0; q < 4; q++) d[mt][nt][q] = 0.f;

    int cpt = K >> 6;                 // chunks of 64

    // loader: per chunk 4096 16B units (Ah 1024, Al 1024, B 2048)
    auto load_chunk = [&](int c, int stage) {
        int kk = c << 6;
        uint32_t sbase = su + stage * 65536;
#pragma unroll
        for (int l = 0; l < 16; l++) {
            int i = tid + l * 256;                    // 0..4095
            if (i < 2048) {                           // A planes
                int sub = i >> 10;                    // 0=Ah 1=Al
                int j = i & 1023;
                int r = j >> 3, u = j & 7;
                uint32_t dst = sbase + sub * 16384 + swz(r, u);
                const __half* Apl = Ab + (size_t)sub * apstride;
                int grow = bm0 + r;
                int pb = (grow < M) ? 16 : 0;
                if (grow >= M) grow = M - 1;
                cp16(dst, Apl + (size_t)grow * K + kk + u * 8, pb);
            } else {                                  // B tile, 256 rows
                int j = i - 2048;
                int r = j >> 3, u = j & 7;
                uint32_t dst = sbase + 32768 + swz(r, u);
                cp16(dst, Bb + (size_t)(bn0 + r) * K + kk + u * 8, 16);
            }
        }
        CP_COMMIT();
    };

    load_chunk(0, 0);

    for (int c = 0; c < cpt; ++c) {
        int stage = c & 1;
        if (c + 1 < cpt) {
            load_chunk(c + 1, stage ^ 1);
            CP_WAIT(1);
        } else {
            CP_WAIT(0);
        }
        __syncthreads();

        uint32_t ah_base = su + stage * 65536;
        uint32_t al_base = ah_base + 16384;
        uint32_t b_base  = ah_base + 32768;

#pragma unroll
        for (int ks = 0; ks < 4; ks++) {
            int c16 = ks * 2 + (lane >> 4);
            uint32_t ah[2][4], al[2][4], bb[4];
#pragma unroll
            for (int mt = 0; mt < 2; mt++) {
                ldsm_x4(ah[mt], ah_base + swz(wm + mt * 16 + (lane & 15), c16));
                ldsm_x4(al[mt], al_base + swz(wm + mt * 16 + (lane & 15), c16));
            }
#pragma unroll
            for (int nt4 = 0; nt4 < 8; nt4++) {
                ldsm_x4(bb, b_base + swz(wn + nt4 * 16 + (lane & 15), c16));
                mma16816(d[0][2 * nt4],     ah[0], bb[0], bb[2]);
                mma16816(d[0][2 * nt4 + 1], ah[0], bb[1], bb[3]);
                mma16816(d[1][2 * nt4],     ah[1], bb[0], bb[2]);
                mma16816(d[1][2 * nt4 + 1], ah[1], bb[1], bb[3]);
                mma16816(d[0][2 * nt4],     al[0], bb[0], bb[2]);
                mma16816(d[0][2 * nt4 + 1], al[0], bb[1], bb[3]);
                mma16816(d[1][2 * nt4],     al[1], bb[0], bb[2]);
                mma16816(d[1][2 * nt4 + 1], al[1], bb[1], bb[3]);
            }
        }
        __syncthreads();
    }

    // epilogue (fragment mapping verified R7-R10)
    int group = lane >> 2, quad = lane & 3;
#pragma unroll
    for (int mt = 0; mt < 2; mt++) {
#pragma unroll
        for (int half = 0; half < 2; half++) {
            int row = bm0 + wm + mt * 16 + group + half * 8;
            if (row >= M) continue;
            float ws = 0.f, wo = 0.f, swf = 0.f, inv = 1.f;
            if (EPI == 1) {
                ws = g_Ws[row]; wo = g_Wo[row];
                swf = expf(CONSTV - g_m[row]);
                inv = 1.f / (ws + wo + swf);
            }
#pragma unroll
            for (int nt = 0; nt < 16; nt++) {
                int col = bn0 + wn + nt * 8 + quad * 2;
                float v0 = d[mt][nt][half * 2 + 0];
                float v1 = d[mt][nt][half * 2 + 1];
                if (EPI == 1) {
                    v0 = (v0 + ws * b2[col]     + wo * b2[col + DV]
                          + swf * X[(size_t)row * DV + col]) * inv;
                    v1 = (v1 + ws * b2[col + 1] + wo * b2[col + 1 + DV]
                          + swf * X[(size_t)row * DV + col + 1]) * inv;
                }
                *reinterpret_cast<float2*>(&C[(size_t)row * N + col]) = make_float2(v0, v1);
            }
        }
    }
}

// ---------------- node-centric accumulation; emits H fp16 planes ----------------
__device__ __forceinline__ void store_split4(size_t elem_off, float4 v) {
    __half a0, a1, b0, b1, c0, c1, d0, d1;
    split2h(v.x, a0, a1); split2h(v.y, b0, b1);
    split2h(v.z, c0, c1); split2h(v.w, d0, d1);
    __half2* p0 = reinterpret_cast<__half2*>(g_HA + elem_off);
    __half2* p1 = reinterpret_cast<__half2*>(g_HA + HSTR + elem_off);
    p0[0] = __halves2half2(a0, b0); p0[1] = __halves2half2(c0, d0);
    p1[0] = __halves2half2(a1, b1); p1[1] = __halves2half2(c1, d1);
}

__global__ void node_kernel(const float* __restrict__ b1, int O) {
    int n    = (blockIdx.x * blockDim.x + threadIdx.x) >> 5;
    int lane = threadIdx.x & 31;
    if (n >= O) return;

    const float4* Pn = reinterpret_cast<const float4*>(g_P + (size_t)n * 1024);
    const float4* B1 = reinterpret_cast<const float4*>(b1);
    float4 ps0[4], ps1[4], bv[4], acc0[4], acc1[4];
#pragma unroll
    for (int j = 0; j < 4; j++) {
        int idx = lane + j * 32;
        ps0[j] = Pn[idx];
        ps1[j] = Pn[128 + idx];
        bv[j]  = B1[idx];
        acc0[j] = make_float4(0.f, 0.f, 0.f, 0.f);
        acc1[j] = make_float4(0.f, 0.f, 0.f, 0.f);
    }
    float wssum = 0.f, wosum = 0.f;
    float mn = g_m[n];
    int beg = g_off[n], end = g_off[n + 1];

    for (int it = beg; it < end; ++it) {
        int2 rec = g_items[it];
        int other = rec.x >> 1, role = rec.x & 1;
        float w = expf(__int_as_float(rec.y) - mn);
        const float4* Po = reinterpret_cast<const float4*>(g_P + (size_t)other * 1024);
        if (role == 0) {
            wssum += w;
#pragma unroll
            for (int j = 0; j < 4; j++) {
                int idx = lane + j * 32;
                float4 q = Po[128 + idx];
                float hx = fmaxf(ps0[j].x + q.x + bv[j].x, 0.f);
                float hy = fmaxf(ps0[j].y + q.y + bv[j].y, 0.f);
                float hz = fmaxf(ps0[j].z + q.z + bv[j].z, 0.f);
                float hw = fmaxf(ps0[j].w + q.w + bv[j].w, 0.f);
                acc0[j].x = fmaf(w, hx, acc0[j].x);
                acc0[j].y = fmaf(w, hy, acc0[j].y);
                acc0[j].z = fmaf(w, hz, acc0[j].z);
                acc0[j].w = fmaf(w, hw, acc0[j].w);
            }
        } else {
            wosum += w;
#pragma unroll
            for (int j = 0; j < 4; j++) {
                int idx = lane + j * 32;
                float4 q = Po[idx];
                float hx = fmaxf(q.x + ps1[j].x + bv[j].x, 0.f);
                float hy = fmaxf(q.y + ps1[j].y + bv[j].y, 0.f);
                float hz = fmaxf(q.z + ps1[j].z + bv[j].z, 0.f);
                float hw = fmaxf(q.w + ps1[j].w + bv[j].w, 0.f);
                acc1[j].x = fmaf(w, hx, acc1[j].x);
                acc1[j].y = fmaf(w, hy, acc1[j].y);
                acc1[j].z = fmaf(w, hz, acc1[j].z);
                acc1[j].w = fmaf(w, hw, acc1[j].w);
            }
        }
    }

    size_t rowbase = (size_t)n * 1024;
#pragma unroll
    for (int j = 0; j < 4; j++) {
        int idx = lane + j * 32;
        store_split4(rowbase + (size_t)idx * 4, acc0[j]);
        store_split4(rowbase + 512 + (size_t)idx * 4, acc1[j]);
    }
    if (lane == 0) { g_Ws[n] = wssum; g_Wo[n] = wosum; }
}

// ---------------- launch ----------------
extern "C" void kernel_launch(void* const* d_in, const int* in_sizes, int n_in,
                              void* d_out, int out_size) {
    const float* X     = (const float*)d_in[0];
    const int*   pairs = (const int*)d_in[1];
    const float* conf  = (const float*)d_in[2];
    const float* W1    = (const float*)d_in[3];
    const float* b1    = (const float*)d_in[4];
    const float* W2    = (const float*)d_in[5];
    const float* b2    = (const float*)d_in[6];
    float*       out   = (float*)d_out;

    int O  = in_sizes[0] / DV;
    int E  = in_sizes[2];
    int MT = (O + 127) / 128;
    const int SMEM = 131072;    // 2 stages x 64KB

    cudaFuncSetAttribute(mma_gemm<0>, cudaFuncAttributeMaxDynamicSharedMemorySize, SMEM);
    cudaFuncSetAttribute(mma_gemm<1>, cudaFuncAttributeMaxDynamicSharedMemorySize, SMEM);

    w_kernel<<<1024, 256>>>(W1, W2);                                     // 1
    split_x_kernel<<<2048, 256>>>(X, O * 128);                           // 2
    init_kernel<<<256, 256>>>(pairs, O);                                 // 3

    // GEMM1: P[O,1024] = X @ W1p, N-tiles of 256  (captured ncu slot)
    mma_gemm<0><<<dim3(4, MT), 256, SMEM>>>(g_XA, XSTR, g_W1Tf,
                                            g_P, O, 1024, 256, nullptr, nullptr); // 4

    edgecvt_kernel<<<(E + 255) / 256, 256>>>(pairs, conf, E);            // 5
    scan_kernel<<<1, 1024>>>(O);                                         // 6
    fill_kernel<<<(E + 255) / 256, 256>>>(conf, E);                      // 7
    node_kernel<<<(O + 7) / 8, 256>>>(b1, O);                            // 8

    // GEMM2: out[O,256] = (H @ W2p + bias/self)/denom, single N-tile
    mma_gemm<1><<<dim3(1, MT), 256, SMEM>>>(g_HA, HSTR, g_W2Tf,
                                            out, O, 256, 1024, X, b2);   // 9
}